// round 1
// baseline (speedup 1.0000x reference)
#include <cuda_runtime.h>

// ---------------------------------------------------------------------------
// Problem constants (hardcoded from reference setup_inputs)
//   x:      (16, 64, 64, 512) fp32
//   w_qkv:  (512, 1536) fp32, b_qkv (1536,)
//   rel_pos:(225, 16) fp32
//   w_out:  (512, 512) fp32, b_out (512,)
//   window 8x8, shift 4, heads 16, hd 32
// ---------------------------------------------------------------------------
#define CC     512
#define NQKV   1536
#define NHEAD  16
#define HD     32
#define NTOK   64
#define MROWS  65536          // 1024 windows * 64 tokens

// Scratch (allocation-free rule: __device__ globals)
__device__ float g_qkv[(size_t)MROWS * NQKV];     // 402 MB: (win,tok) x (q|k|v, head, d)
__device__ float g_att[(size_t)MROWS * CC];       // 134 MB: (win,tok) x (head, d)
__device__ float g_bias[NHEAD * NTOK * NTOK];     // 256 KB: (head, q, k)

// ---------------------------------------------------------------------------
// Kernel 0: relative-position bias table  bias[h][q][k] = rel_pos[idx(q,k)][h]
// ---------------------------------------------------------------------------
__global__ void bias_kernel(const float* __restrict__ rel_pos)
{
    int i = blockIdx.x * blockDim.x + threadIdx.x;      // 65536 total
    int head = i >> 12;
    int q = (i >> 6) & 63;
    int k = i & 63;
    int qi = q >> 3, qj = q & 7, ki = k >> 3, kj = k & 7;
    int idx = (qi - ki + 7) * 15 + (qj - kj + 7);       // (2p-1)=15
    g_bias[i] = rel_pos[idx * NHEAD + head];
}

// ---------------------------------------------------------------------------
// Kernel 1: fused cyclic-shift + window-partition gather + QKV GEMM
//   out[m, n] = sum_k X[m,k] * w_qkv[k,n] + b_qkv[n]
//   m = win*64 + tok; source pixel h=(wh*8+ph+4)&63, w=(ww*8+pw+4)&63
//   BM=128, BN=128, BK=16, 256 threads, 8x8 per-thread microtile
// ---------------------------------------------------------------------------
__global__ __launch_bounds__(256, 2)
void qkv_gemm_kernel(const float* __restrict__ x,
                     const float* __restrict__ wqkv,
                     const float* __restrict__ bqkv)
{
    __shared__ float As[16][132];   // [k][m], padded (STS conflict-cheap, LDS.128-aligned)
    __shared__ float Bs[16][128];   // [k][n]

    const int bn = blockIdx.x;      // 0..11
    const int bm = blockIdx.y;      // 0..511
    const int tid = threadIdx.x;

    // A loader mapping: 512 float4 per tile, 2 per thread
    const int a_row0 = tid >> 2;            // 0..63 (and +64)
    const int a_kq   = (tid & 3) * 4;       // 0,4,8,12

    const float* arow_ptr[2];
    #pragma unroll
    for (int r = 0; r < 2; r++) {
        int m   = bm * 128 + a_row0 + r * 64;
        int win = m >> 6, t = m & 63;
        int b   = win >> 6, whi = (win >> 3) & 7, wwi = win & 7;
        int ph  = t >> 3, pw = t & 7;
        int h   = (whi * 8 + ph + 4) & 63;
        int w   = (wwi * 8 + pw + 4) & 63;
        arow_ptr[r] = x + ((size_t)((b * 64 + h) * 64 + w)) * CC;
    }

    // B loader mapping: rows (tid>>5) and (tid>>5)+8, 32 float4 across N
    const int b_row = tid >> 5;             // 0..7
    const int b_nq  = (tid & 31) * 4;
    const float* bbase = wqkv + bn * 128 + b_nq;

    float acc[8][8];
    #pragma unroll
    for (int i = 0; i < 8; i++)
        #pragma unroll
        for (int j = 0; j < 8; j++) acc[i][j] = 0.0f;

    const int ty = tid >> 4, tx = tid & 15;
    const int msub = ty * 8, nsub = tx * 8;

    for (int k0 = 0; k0 < CC; k0 += 16) {
        #pragma unroll
        for (int r = 0; r < 2; r++) {
            float4 av = *(const float4*)(arow_ptr[r] + k0 + a_kq);
            int row = a_row0 + r * 64;
            As[a_kq + 0][row] = av.x;
            As[a_kq + 1][row] = av.y;
            As[a_kq + 2][row] = av.z;
            As[a_kq + 3][row] = av.w;
        }
        #pragma unroll
        for (int r = 0; r < 2; r++) {
            int kr = b_row + r * 8;
            float4 bv = *(const float4*)(bbase + (size_t)(k0 + kr) * NQKV);
            *(float4*)&Bs[kr][b_nq] = bv;
        }
        __syncthreads();
        #pragma unroll
        for (int kk = 0; kk < 16; kk++) {
            float a[8], bb[8];
            *(float4*)&a[0]  = *(const float4*)&As[kk][msub];
            *(float4*)&a[4]  = *(const float4*)&As[kk][msub + 4];
            *(float4*)&bb[0] = *(const float4*)&Bs[kk][nsub];
            *(float4*)&bb[4] = *(const float4*)&Bs[kk][nsub + 4];
            #pragma unroll
            for (int i = 0; i < 8; i++)
                #pragma unroll
                for (int j = 0; j < 8; j++)
                    acc[i][j] = fmaf(a[i], bb[j], acc[i][j]);
        }
        __syncthreads();
    }

    const int ncol = bn * 128 + nsub;
    float bias0[8];
    #pragma unroll
    for (int j = 0; j < 8; j++) bias0[j] = bqkv[ncol + j];

    #pragma unroll
    for (int i = 0; i < 8; i++) {
        int m = bm * 128 + msub + i;
        float* dst = g_qkv + (size_t)m * NQKV + ncol;
        float4 v0, v1;
        v0.x = acc[i][0] + bias0[0];  v0.y = acc[i][1] + bias0[1];
        v0.z = acc[i][2] + bias0[2];  v0.w = acc[i][3] + bias0[3];
        v1.x = acc[i][4] + bias0[4];  v1.y = acc[i][5] + bias0[5];
        v1.z = acc[i][6] + bias0[6];  v1.w = acc[i][7] + bias0[7];
        *(float4*)dst       = v0;
        *(float4*)(dst + 4) = v1;
    }
}

// ---------------------------------------------------------------------------
// Kernel 2: windowed attention. One CTA per (window, head), 64 threads
// (one query row per thread). k/v staged in smem; scores in padded smem.
// ---------------------------------------------------------------------------
__global__ __launch_bounds__(64)
void attn_kernel()
{
    __shared__ float ks[64][36];   // pad 36: float4-aligned rows, broadcast reads
    __shared__ float vs[64][36];
    __shared__ float ss[64][65];   // scores, pad 65: conflict-free column access

    const int win  = blockIdx.x;     // 0..1023
    const int head = blockIdx.y;     // 0..15
    const int t    = threadIdx.x;    // 0..63

    const float* base = g_qkv + (size_t)(win * 64) * NQKV + head * HD;

    // load my q row, and my row of k/v into smem
    float qreg[32];
    {
        const float* qp = base + (size_t)t * NQKV;          // q at col offset 0
        const float* kp = qp + 512;
        const float* vp = qp + 1024;
        #pragma unroll
        for (int d4 = 0; d4 < 8; d4++) {
            float4 qv = *(const float4*)(qp + d4 * 4);
            qreg[d4 * 4 + 0] = qv.x; qreg[d4 * 4 + 1] = qv.y;
            qreg[d4 * 4 + 2] = qv.z; qreg[d4 * 4 + 3] = qv.w;
            float4 kv = *(const float4*)(kp + d4 * 4);
            ks[t][d4 * 4 + 0] = kv.x; ks[t][d4 * 4 + 1] = kv.y;
            ks[t][d4 * 4 + 2] = kv.z; ks[t][d4 * 4 + 3] = kv.w;
            float4 vv = *(const float4*)(vp + d4 * 4);
            vs[t][d4 * 4 + 0] = vv.x; vs[t][d4 * 4 + 1] = vv.y;
            vs[t][d4 * 4 + 2] = vv.z; vs[t][d4 * 4 + 3] = vv.w;
        }
    }
    __syncthreads();

    const float scale = 0.17677669529663687f;   // 1/sqrt(32)
    const float* biasrow = g_bias + ((head * 64) + t) * 64;

    // S = q k^T * scale + bias
    for (int kk = 0; kk < 64; kk++) {
        float acc = 0.0f;
        #pragma unroll
        for (int d4 = 0; d4 < 8; d4++) {
            float4 kv = *(const float4*)&ks[kk][d4 * 4];
            acc = fmaf(qreg[d4 * 4 + 0], kv.x, acc);
            acc = fmaf(qreg[d4 * 4 + 1], kv.y, acc);
            acc = fmaf(qreg[d4 * 4 + 2], kv.z, acc);
            acc = fmaf(qreg[d4 * 4 + 3], kv.w, acc);
        }
        ss[t][kk] = acc * scale + biasrow[kk];
    }

    // softmax over row
    float mx = -1e30f;
    for (int kk = 0; kk < 64; kk++) mx = fmaxf(mx, ss[t][kk]);
    float sum = 0.0f;
    for (int kk = 0; kk < 64; kk++) {
        float e = __expf(ss[t][kk] - mx);
        ss[t][kk] = e;
        sum += e;
    }
    const float inv = 1.0f / sum;

    // O = P @ V
    float o[32];
    #pragma unroll
    for (int d = 0; d < 32; d++) o[d] = 0.0f;
    for (int kk = 0; kk < 64; kk++) {
        float p = ss[t][kk];
        #pragma unroll
        for (int d4 = 0; d4 < 8; d4++) {
            float4 vv = *(const float4*)&vs[kk][d4 * 4];
            o[d4 * 4 + 0] = fmaf(p, vv.x, o[d4 * 4 + 0]);
            o[d4 * 4 + 1] = fmaf(p, vv.y, o[d4 * 4 + 1]);
            o[d4 * 4 + 2] = fmaf(p, vv.z, o[d4 * 4 + 2]);
            o[d4 * 4 + 3] = fmaf(p, vv.w, o[d4 * 4 + 3]);
        }
    }

    float* op = g_att + (size_t)(win * 64 + t) * CC + head * HD;
    #pragma unroll
    for (int d4 = 0; d4 < 8; d4++) {
        float4 v;
        v.x = o[d4 * 4 + 0] * inv; v.y = o[d4 * 4 + 1] * inv;
        v.z = o[d4 * 4 + 2] * inv; v.w = o[d4 * 4 + 3] * inv;
        *(float4*)(op + d4 * 4) = v;
    }
}

// ---------------------------------------------------------------------------
// Kernel 3: out projection + bias + reverse window-partition + reverse shift
//   out_pix[b, (hs+4)&63, (ws+4)&63, n] = (g_att @ w_out)[m, n] + b_out[n]
// ---------------------------------------------------------------------------
__global__ __launch_bounds__(256, 2)
void out_gemm_kernel(const float* __restrict__ wout,
                     const float* __restrict__ bout,
                     float* __restrict__ out)
{
    __shared__ float As[16][132];
    __shared__ float Bs[16][128];

    const int bn = blockIdx.x;      // 0..3
    const int bm = blockIdx.y;      // 0..511
    const int tid = threadIdx.x;

    const int a_row0 = tid >> 2;
    const int a_kq   = (tid & 3) * 4;

    const float* arow_ptr[2];
    #pragma unroll
    for (int r = 0; r < 2; r++) {
        int m = bm * 128 + a_row0 + r * 64;
        arow_ptr[r] = g_att + (size_t)m * CC;
    }

    const int b_row = tid >> 5;
    const int b_nq  = (tid & 31) * 4;
    const float* bbase = wout + bn * 128 + b_nq;

    float acc[8][8];
    #pragma unroll
    for (int i = 0; i < 8; i++)
        #pragma unroll
        for (int j = 0; j < 8; j++) acc[i][j] = 0.0f;

    const int ty = tid >> 4, tx = tid & 15;
    const int msub = ty * 8, nsub = tx * 8;

    for (int k0 = 0; k0 < CC; k0 += 16) {
        #pragma unroll
        for (int r = 0; r < 2; r++) {
            float4 av = *(const float4*)(arow_ptr[r] + k0 + a_kq);
            int row = a_row0 + r * 64;
            As[a_kq + 0][row] = av.x;
            As[a_kq + 1][row] = av.y;
            As[a_kq + 2][row] = av.z;
            As[a_kq + 3][row] = av.w;
        }
        #pragma unroll
        for (int r = 0; r < 2; r++) {
            int kr = b_row + r * 8;
            float4 bv = *(const float4*)(bbase + (size_t)(k0 + kr) * CC);
            *(float4*)&Bs[kr][b_nq] = bv;
        }
        __syncthreads();
        #pragma unroll
        for (int kk = 0; kk < 16; kk++) {
            float a[8], bb[8];
            *(float4*)&a[0]  = *(const float4*)&As[kk][msub];
            *(float4*)&a[4]  = *(const float4*)&As[kk][msub + 4];
            *(float4*)&bb[0] = *(const float4*)&Bs[kk][nsub];
            *(float4*)&bb[4] = *(const float4*)&Bs[kk][nsub + 4];
            #pragma unroll
            for (int i = 0; i < 8; i++)
                #pragma unroll
                for (int j = 0; j < 8; j++)
                    acc[i][j] = fmaf(a[i], bb[j], acc[i][j]);
        }
        __syncthreads();
    }

    const int ncol = bn * 128 + nsub;
    float bias0[8];
    #pragma unroll
    for (int j = 0; j < 8; j++) bias0[j] = bout[ncol + j];

    #pragma unroll
    for (int i = 0; i < 8; i++) {
        int m   = bm * 128 + msub + i;
        int win = m >> 6, t = m & 63;
        int b   = win >> 6, whi = (win >> 3) & 7, wwi = win & 7;
        int ph  = t >> 3, pw = t & 7;
        int hs  = whi * 8 + ph;
        int wsp = wwi * 8 + pw;
        int ho  = (hs + 4) & 63;
        int wo  = (wsp + 4) & 63;
        float* dst = out + ((size_t)((b * 64 + ho) * 64 + wo)) * CC + ncol;
        float4 v0, v1;
        v0.x = acc[i][0] + bias0[0];  v0.y = acc[i][1] + bias0[1];
        v0.z = acc[i][2] + bias0[2];  v0.w = acc[i][3] + bias0[3];
        v1.x = acc[i][4] + bias0[4];  v1.y = acc[i][5] + bias0[5];
        v1.z = acc[i][6] + bias0[6];  v1.w = acc[i][7] + bias0[7];
        *(float4*)dst       = v0;
        *(float4*)(dst + 4) = v1;
    }
}

// ---------------------------------------------------------------------------
// launch
// ---------------------------------------------------------------------------
extern "C" void kernel_launch(void* const* d_in, const int* in_sizes, int n_in,
                              void* d_out, int out_size)
{
    const float* x       = (const float*)d_in[0];
    const float* w_qkv   = (const float*)d_in[1];
    const float* b_qkv   = (const float*)d_in[2];
    const float* rel_pos = (const float*)d_in[3];
    const float* w_out   = (const float*)d_in[4];
    const float* b_out   = (const float*)d_in[5];
    float* out = (float*)d_out;

    bias_kernel<<<64, 1024>>>(rel_pos);
    qkv_gemm_kernel<<<dim3(NQKV / 128, MROWS / 128), 256>>>(x, w_qkv, b_qkv);
    attn_kernel<<<dim3(1024, NHEAD), 64>>>();
    out_gemm_kernel<<<dim3(CC / 128, MROWS / 128), 256>>>(w_out, b_out, out);
}

// round 3
// speedup vs baseline: 1.6951x; 1.6951x over previous
#include <cuda_runtime.h>
#include <cuda_bf16.h>
#include <cstdint>

// ---------------------------------------------------------------------------
// WMSA: B=16 H=W=64 C=512, window 8x8 (shift 4), 16 heads x 32
//   GEMM1: (65536 x 512) @ (512 x 1536) -> g_qkv       [mma.sync bf16 3-split]
//   attn : per (window, head) 64x64                     [fp32 SIMT]
//   GEMM2: (65536 x 512) @ (512 x 512)  -> out scatter  [mma.sync bf16 3-split]
// ---------------------------------------------------------------------------
#define CC     512
#define NQKV   1536
#define NHEAD  16
#define MROWS  65536

__device__ float g_qkv[(size_t)MROWS * NQKV];
__device__ float g_att[(size_t)MROWS * CC];
__device__ float g_bias[NHEAD * 64 * 64];
// pre-transposed + hi/lo split weights: wt[n][k] = w[k][n]
__device__ __nv_bfloat16 g_wqkv_hi[(size_t)NQKV * CC];
__device__ __nv_bfloat16 g_wqkv_lo[(size_t)NQKV * CC];
__device__ __nv_bfloat16 g_wout_hi[(size_t)CC * CC];
__device__ __nv_bfloat16 g_wout_lo[(size_t)CC * CC];

// ------------------------------- helpers -----------------------------------
__device__ __forceinline__ uint32_t smem_u32(const void* p) {
    uint32_t a;
    asm("{ .reg .u64 t; cvta.to.shared.u64 t, %1; cvt.u32.u64 %0, t; }"
        : "=r"(a) : "l"(p));
    return a;
}
__device__ __forceinline__ uint32_t pack2(float a, float b) {
    __nv_bfloat162 h = __floats2bfloat162_rn(a, b);
    return *(uint32_t*)&h;
}
__device__ __forceinline__ void cvt8(const float4& v0, const float4& v1,
                                     uint4& hp, uint4& lp) {
    float vv[8] = { v0.x, v0.y, v0.z, v0.w, v1.x, v1.y, v1.z, v1.w };
    float hh[8];
    #pragma unroll
    for (int e = 0; e < 8; e++)
        hh[e] = __bfloat162float(__float2bfloat16(vv[e]));
    hp.x = pack2(hh[0], hh[1]); hp.y = pack2(hh[2], hh[3]);
    hp.z = pack2(hh[4], hh[5]); hp.w = pack2(hh[6], hh[7]);
    lp.x = pack2(vv[0] - hh[0], vv[1] - hh[1]);
    lp.y = pack2(vv[2] - hh[2], vv[3] - hh[3]);
    lp.z = pack2(vv[4] - hh[4], vv[5] - hh[5]);
    lp.w = pack2(vv[6] - hh[6], vv[7] - hh[7]);
}

#define LDSM4(r0, r1, r2, r3, addr) \
    asm volatile("ldmatrix.sync.aligned.m8n8.x4.shared.b16 {%0,%1,%2,%3}, [%4];" \
        : "=r"(r0), "=r"(r1), "=r"(r2), "=r"(r3) : "r"(addr))

#define MMA16816(d, a, b) \
    asm volatile("mma.sync.aligned.m16n8k16.row.col.f32.bf16.bf16.f32 " \
        "{%0,%1,%2,%3}, {%4,%5,%6,%7}, {%8,%9}, {%0,%1,%2,%3};" \
        : "+f"((d)[0]), "+f"((d)[1]), "+f"((d)[2]), "+f"((d)[3]) \
        : "r"((a)[0]), "r"((a)[1]), "r"((a)[2]), "r"((a)[3]), \
          "r"((b)[0]), "r"((b)[1]))

#define CPASYNC16(smem, gmem) \
    asm volatile("cp.async.cg.shared.global [%0], [%1], 16;" \
        :: "r"(smem), "l"(gmem) : "memory")
#define CPCOMMIT() asm volatile("cp.async.commit_group;" ::: "memory")
#define CPWAIT0()  asm volatile("cp.async.wait_group 0;" ::: "memory")

// ---------------------------------------------------------------------------
// Kernel 0: relative-position bias table
// ---------------------------------------------------------------------------
__global__ void bias_kernel(const float* __restrict__ rel_pos)
{
    int i = blockIdx.x * blockDim.x + threadIdx.x;
    int head = i >> 12;
    int q = (i >> 6) & 63, k = i & 63;
    int qi = q >> 3, qj = q & 7, ki = k >> 3, kj = k & 7;
    int idx = (qi - ki + 7) * 15 + (qj - kj + 7);
    g_bias[i] = rel_pos[idx * NHEAD + head];
}

// ---------------------------------------------------------------------------
// Kernel 0b: transpose + hi/lo split of weights: wt[n][k] = w[k][n]
// ---------------------------------------------------------------------------
__global__ void wsplit_qkv_kernel(const float* __restrict__ w)
{
    int i = blockIdx.x * blockDim.x + threadIdx.x;   // NQKV*512
    int n = i >> 9, k = i & 511;
    float v = w[(size_t)k * NQKV + n];
    __nv_bfloat16 h = __float2bfloat16(v);
    g_wqkv_hi[i] = h;
    g_wqkv_lo[i] = __float2bfloat16(v - __bfloat162float(h));
}
__global__ void wsplit_out_kernel(const float* __restrict__ w)
{
    int i = blockIdx.x * blockDim.x + threadIdx.x;   // 512*512
    int n = i >> 9, k = i & 511;
    float v = w[(size_t)k * CC + n];
    __nv_bfloat16 h = __float2bfloat16(v);
    g_wout_hi[i] = h;
    g_wout_lo[i] = __float2bfloat16(v - __bfloat162float(h));
}

// ---------------------------------------------------------------------------
// mma.sync GEMM: C[m, n0:n0+128] = A[m, :512] @ W[:, n0:n0+128] + bias
//   MODE 0: A = shift-gathered x, C -> g_qkv
//   MODE 1: A = g_att rows,       C -> scatter d_out (reverse shift)
//   CTA 128x128, chunk = 32 fp32 k; bf16 3-term split; 2-stage pipeline.
//   smem rows padded to 80B: (20r+4u) mod 32 is a perfect bank partition ->
//   conflict-free ldmatrix AND conflict-free STS, no XOR swizzle.
// ---------------------------------------------------------------------------
#define RSTRIDE 80
#define T_AH    0
#define T_AL    10240
#define T_BH    20480
#define T_BL    30720
#define STAGE   40960
#define NCHUNK  16

template<int MODE>
__global__ __launch_bounds__(256)
void mma_gemm_kernel(const float* __restrict__ x,
                     const float* __restrict__ bias,
                     float* __restrict__ outp)
{
    extern __shared__ __align__(16) char dsa[];
    const uint32_t sb = smem_u32(dsa);

    const int tid  = threadIdx.x;
    const int lane = tid & 31, wid = tid >> 5;
    const int lr   = lane & 7;          // row-within-8
    const int lu   = lane >> 3;         // 16B unit 0..3
    const int bm   = blockIdx.y;
    const int n0   = blockIdx.x * 128;

    // ---- A loader: 2 passes of 64 rows; thread -> (row, 8-fp32 unit) ----
    const float* aptr[2];
    uint32_t a_sts[2];
    #pragma unroll
    for (int p = 0; p < 2; p++) {
        int rt = p * 64 + wid * 8 + lr;
        int m  = bm * 128 + rt;
        const float* rp;
        if (MODE == 0) {
            int win = m >> 6, t = m & 63;
            int b = win >> 6, whi = (win >> 3) & 7, wwi = win & 7;
            int ph = t >> 3, pw = t & 7;
            int h = (whi * 8 + ph + 4) & 63;
            int w = (wwi * 8 + pw + 4) & 63;
            rp = x + ((size_t)((b * 64 + h) * 64 + w)) * CC;
        } else {
            rp = g_att + (size_t)m * CC;
        }
        aptr[p]  = rp + lu * 8;
        a_sts[p] = (uint32_t)rt * RSTRIDE + lu * 16;
    }
    // ---- B loader: 4 passes (hi rows 0-63, hi 64-127, lo 0-63, lo 64-127) --
    const __nv_bfloat16* bptr[4];
    uint32_t b_sts[4];
    #pragma unroll
    for (int q = 0; q < 4; q++) {
        int rt = (q & 1) * 64 + wid * 8 + lr;
        const __nv_bfloat16* wt = (MODE == 0)
            ? (q < 2 ? g_wqkv_hi : g_wqkv_lo)
            : (q < 2 ? g_wout_hi : g_wout_lo);
        bptr[q]  = wt + (size_t)(n0 + rt) * CC + lu * 8;
        b_sts[q] = (q < 2 ? T_BH : T_BL) + (uint32_t)rt * RSTRIDE + lu * 16;
    }

    float acc[4][4][4];
    #pragma unroll
    for (int i = 0; i < 4; i++)
        #pragma unroll
        for (int j = 0; j < 4; j++)
            #pragma unroll
            for (int e = 0; e < 4; e++) acc[i][j][e] = 0.0f;

    const int wm = wid >> 2;   // 0..1 : m-half (64 rows)
    const int wn = wid & 3;    // 0..3 : n-quarter (32 cols)

    // ---- prologue: chunk 0 ----
    #pragma unroll
    for (int q = 0; q < 4; q++) CPASYNC16(sb + b_sts[q], bptr[q]);
    CPCOMMIT();
    float4 pre[2][2];
    #pragma unroll
    for (int p = 0; p < 2; p++) {
        pre[p][0] = *(const float4*)(aptr[p]);
        pre[p][1] = *(const float4*)(aptr[p] + 4);
    }
    #pragma unroll
    for (int p = 0; p < 2; p++) {
        uint4 hp, lp; cvt8(pre[p][0], pre[p][1], hp, lp);
        *(uint4*)(dsa + T_AH + a_sts[p]) = hp;
        *(uint4*)(dsa + T_AL + a_sts[p]) = lp;
    }
    CPWAIT0();
    __syncthreads();

    // ---- mainloop ----
    for (int c = 0; c < NCHUNK; c++) {
        const int s = c & 1;
        const uint32_t stg = sb + (uint32_t)s * STAGE;

        if (c + 1 < NCHUNK) {
            const uint32_t nst = (uint32_t)(s ^ 1) * STAGE;
            #pragma unroll
            for (int q = 0; q < 4; q++)
                CPASYNC16(sb + nst + b_sts[q], bptr[q] + (c + 1) * 32);
            CPCOMMIT();
            #pragma unroll
            for (int p = 0; p < 2; p++) {
                pre[p][0] = *(const float4*)(aptr[p] + (c + 1) * 32);
                pre[p][1] = *(const float4*)(aptr[p] + (c + 1) * 32 + 4);
            }
        }

        // compute chunk c: 3 bf16 terms over 2 k16 steps
        #pragma unroll
        for (int k16 = 0; k16 < 2; k16++) {
            uint32_t A[4][4], Bh[2][4], Bl[2][4];
            const uint32_t a_off =
                (uint32_t)(wm * 64 + (lane & 15)) * RSTRIDE
                + (uint32_t)(k16 * 2 + (lane >> 4)) * 16;
            #pragma unroll
            for (int i = 0; i < 4; i++)
                LDSM4(A[i][0], A[i][1], A[i][2], A[i][3],
                      stg + T_AH + a_off + i * 16 * RSTRIDE);
            const int mi = lane >> 3;
            const uint32_t b_off =
                (uint32_t)(wn * 32 + ((mi >> 1) << 3) + (lane & 7)) * RSTRIDE
                + (uint32_t)(k16 * 2 + (mi & 1)) * 16;
            #pragma unroll
            for (int jp = 0; jp < 2; jp++)
                LDSM4(Bh[jp][0], Bh[jp][1], Bh[jp][2], Bh[jp][3],
                      stg + T_BH + b_off + jp * 16 * RSTRIDE);
            #pragma unroll
            for (int jp = 0; jp < 2; jp++)
                LDSM4(Bl[jp][0], Bl[jp][1], Bl[jp][2], Bl[jp][3],
                      stg + T_BL + b_off + jp * 16 * RSTRIDE);

            #pragma unroll
            for (int i = 0; i < 4; i++)
                #pragma unroll
                for (int j = 0; j < 4; j++)
                    MMA16816(acc[i][j], A[i], &Bh[j >> 1][(j & 1) * 2]);
            #pragma unroll
            for (int i = 0; i < 4; i++)
                #pragma unroll
                for (int j = 0; j < 4; j++)
                    MMA16816(acc[i][j], A[i], &Bl[j >> 1][(j & 1) * 2]);
            // overwrite A with A-lo, multiply by B-hi
            #pragma unroll
            for (int i = 0; i < 4; i++)
                LDSM4(A[i][0], A[i][1], A[i][2], A[i][3],
                      stg + T_AL + a_off + i * 16 * RSTRIDE);
            #pragma unroll
            for (int i = 0; i < 4; i++)
                #pragma unroll
                for (int j = 0; j < 4; j++)
                    MMA16816(acc[i][j], A[i], &Bh[j >> 1][(j & 1) * 2]);
        }

        if (c + 1 < NCHUNK) {
            #pragma unroll
            for (int p = 0; p < 2; p++) {
                uint4 hp, lp; cvt8(pre[p][0], pre[p][1], hp, lp);
                char* d = dsa + (size_t)(s ^ 1) * STAGE;
                *(uint4*)(d + T_AH + a_sts[p]) = hp;
                *(uint4*)(d + T_AL + a_sts[p]) = lp;
            }
            CPWAIT0();
            __syncthreads();
        }
    }

    // ---- epilogue: direct register -> gmem, bias fused ----
    float2 bj4[4];
    #pragma unroll
    for (int j = 0; j < 4; j++)
        bj4[j] = *(const float2*)(bias + n0 + wn * 32 + j * 8 + (lane & 3) * 2);

    #pragma unroll
    for (int i = 0; i < 4; i++) {
        #pragma unroll
        for (int half = 0; half < 2; half++) {
            int m = bm * 128 + wm * 64 + i * 16 + half * 8 + (lane >> 2);
            float* drow;
            if (MODE == 0) {
                drow = g_qkv + (size_t)m * NQKV;
            } else {
                int win = m >> 6, t = m & 63;
                int b = win >> 6, whi = (win >> 3) & 7, wwi = win & 7;
                int ph = t >> 3, pw = t & 7;
                int ho = (whi * 8 + ph + 4) & 63;
                int wo = (wwi * 8 + pw + 4) & 63;
                drow = outp + ((size_t)((b * 64 + ho) * 64 + wo)) * CC;
            }
            #pragma unroll
            for (int j = 0; j < 4; j++) {
                int cb = n0 + wn * 32 + j * 8 + (lane & 3) * 2;
                float2 v;
                v.x = acc[i][j][half * 2 + 0] + bj4[j].x;
                v.y = acc[i][j][half * 2 + 1] + bj4[j].y;
                *(float2*)(drow + cb) = v;
            }
        }
    }
}

// ---------------------------------------------------------------------------
// attention (unchanged R1 version)
// ---------------------------------------------------------------------------
__global__ __launch_bounds__(64)
void attn_kernel()
{
    __shared__ float ks[64][36];
    __shared__ float vs[64][36];
    __shared__ float ss[64][65];

    const int win  = blockIdx.x;
    const int head = blockIdx.y;
    const int t    = threadIdx.x;

    const float* base = g_qkv + (size_t)(win * 64) * NQKV + head * 32;

    float qreg[32];
    {
        const float* qp = base + (size_t)t * NQKV;
        const float* kp = qp + 512;
        const float* vp = qp + 1024;
        #pragma unroll
        for (int d4 = 0; d4 < 8; d4++) {
            float4 qv = *(const float4*)(qp + d4 * 4);
            qreg[d4 * 4 + 0] = qv.x; qreg[d4 * 4 + 1] = qv.y;
            qreg[d4 * 4 + 2] = qv.z; qreg[d4 * 4 + 3] = qv.w;
            float4 kv = *(const float4*)(kp + d4 * 4);
            ks[t][d4 * 4 + 0] = kv.x; ks[t][d4 * 4 + 1] = kv.y;
            ks[t][d4 * 4 + 2] = kv.z; ks[t][d4 * 4 + 3] = kv.w;
            float4 vv = *(const float4*)(vp + d4 * 4);
            vs[t][d4 * 4 + 0] = vv.x; vs[t][d4 * 4 + 1] = vv.y;
            vs[t][d4 * 4 + 2] = vv.z; vs[t][d4 * 4 + 3] = vv.w;
        }
    }
    __syncthreads();

    const float scale = 0.17677669529663687f;
    const float* biasrow = g_bias + ((head * 64) + t) * 64;

    for (int kk = 0; kk < 64; kk++) {
        float acc = 0.0f;
        #pragma unroll
        for (int d4 = 0; d4 < 8; d4++) {
            float4 kv = *(const float4*)&ks[kk][d4 * 4];
            acc = fmaf(qreg[d4 * 4 + 0], kv.x, acc);
            acc = fmaf(qreg[d4 * 4 + 1], kv.y, acc);
            acc = fmaf(qreg[d4 * 4 + 2], kv.z, acc);
            acc = fmaf(qreg[d4 * 4 + 3], kv.w, acc);
        }
        ss[t][kk] = acc * scale + biasrow[kk];
    }

    float mx = -1e30f;
    for (int kk = 0; kk < 64; kk++) mx = fmaxf(mx, ss[t][kk]);
    float sum = 0.0f;
    for (int kk = 0; kk < 64; kk++) {
        float e = __expf(ss[t][kk] - mx);
        ss[t][kk] = e;
        sum += e;
    }
    const float inv = 1.0f / sum;

    float o[32];
    #pragma unroll
    for (int d = 0; d < 32; d++) o[d] = 0.0f;
    for (int kk = 0; kk < 64; kk++) {
        float p = ss[t][kk];
        #pragma unroll
        for (int d4 = 0; d4 < 8; d4++) {
            float4 vv = *(const float4*)&vs[kk][d4 * 4];
            o[d4 * 4 + 0] = fmaf(p, vv.x, o[d4 * 4 + 0]);
            o[d4 * 4 + 1] = fmaf(p, vv.y, o[d4 * 4 + 1]);
            o[d4 * 4 + 2] = fmaf(p, vv.z, o[d4 * 4 + 2]);
            o[d4 * 4 + 3] = fmaf(p, vv.w, o[d4 * 4 + 3]);
        }
    }

    float* op = g_att + (size_t)(win * 64 + t) * CC + head * 32;
    #pragma unroll
    for (int d4 = 0; d4 < 8; d4++) {
        float4 v;
        v.x = o[d4 * 4 + 0] * inv; v.y = o[d4 * 4 + 1] * inv;
        v.z = o[d4 * 4 + 2] * inv; v.w = o[d4 * 4 + 3] * inv;
        *(float4*)(op + d4 * 4) = v;
    }
}

// ---------------------------------------------------------------------------
// launch
// ---------------------------------------------------------------------------
extern "C" void kernel_launch(void* const* d_in, const int* in_sizes, int n_in,
                              void* d_out, int out_size)
{
    const float* x       = (const float*)d_in[0];
    const float* w_qkv   = (const float*)d_in[1];
    const float* b_qkv   = (const float*)d_in[2];
    const float* rel_pos = (const float*)d_in[3];
    const float* w_out   = (const float*)d_in[4];
    const float* b_out   = (const float*)d_in[5];
    float* out = (float*)d_out;

    const int dyn = 2 * STAGE;      // 81920 bytes
    cudaFuncSetAttribute(mma_gemm_kernel<0>,
                         cudaFuncAttributeMaxDynamicSharedMemorySize, dyn);
    cudaFuncSetAttribute(mma_gemm_kernel<1>,
                         cudaFuncAttributeMaxDynamicSharedMemorySize, dyn);

    bias_kernel<<<64, 1024>>>(rel_pos);
    wsplit_qkv_kernel<<<(NQKV * CC) / 256, 256>>>(w_qkv);
    wsplit_out_kernel<<<(CC * CC) / 256, 256>>>(w_out);

    mma_gemm_kernel<0><<<dim3(NQKV / 128, MROWS / 128), 256, dyn>>>(x, b_qkv, nullptr);
    attn_kernel<<<dim3(1024, NHEAD), 64>>>();
    mma_gemm_kernel<1><<<dim3(CC / 128, MROWS / 128), 256, dyn>>>(nullptr, b_out, out);
}

// round 4
// speedup vs baseline: 1.9056x; 1.1242x over previous
#include <cuda_runtime.h>
#include <cuda_bf16.h>
#include <cstdint>

// ---------------------------------------------------------------------------
// WMSA: B=16 H=W=64 C=512, window 8x8 (shift 4), 16 heads x 32
//   pre:   gather+split x -> g_a_hi/lo (bf16), weights -> transposed hi/lo
//   GEMM1: (65536 x 512) @ (512 x 1536) -> g_qkv fp32   [mma.sync 3-term bf16]
//   attn : per (window, head) 64x64, scores in regs -> g_o_hi/lo (bf16 split)
//   GEMM2: (65536 x 512) @ (512 x 512)  -> out scatter  [mma.sync 3-term bf16]
// ---------------------------------------------------------------------------
#define CC     512
#define NQKV   1536
#define NHEAD  16
#define MROWS  65536

__device__ float g_qkv[(size_t)MROWS * NQKV];
__device__ float g_bias[NHEAD * 64 * 64];
// GEMM A operands, pre-split bf16
__device__ __nv_bfloat16 g_a_hi[(size_t)MROWS * CC];
__device__ __nv_bfloat16 g_a_lo[(size_t)MROWS * CC];
__device__ __nv_bfloat16 g_o_hi[(size_t)MROWS * CC];
__device__ __nv_bfloat16 g_o_lo[(size_t)MROWS * CC];
// pre-transposed + hi/lo split weights: wt[n][k] = w[k][n]
__device__ __nv_bfloat16 g_wqkv_hi[(size_t)NQKV * CC];
__device__ __nv_bfloat16 g_wqkv_lo[(size_t)NQKV * CC];
__device__ __nv_bfloat16 g_wout_hi[(size_t)CC * CC];
__device__ __nv_bfloat16 g_wout_lo[(size_t)CC * CC];

// ------------------------------- helpers -----------------------------------
__device__ __forceinline__ uint32_t smem_u32(const void* p) {
    uint32_t a;
    asm("{ .reg .u64 t; cvta.to.shared.u64 t, %1; cvt.u32.u64 %0, t; }"
        : "=r"(a) : "l"(p));
    return a;
}
__device__ __forceinline__ uint32_t pack2(float a, float b) {
    __nv_bfloat162 h = __floats2bfloat162_rn(a, b);
    return *(uint32_t*)&h;
}

#define LDSM4(r0, r1, r2, r3, addr) \
    asm volatile("ldmatrix.sync.aligned.m8n8.x4.shared.b16 {%0,%1,%2,%3}, [%4];" \
        : "=r"(r0), "=r"(r1), "=r"(r2), "=r"(r3) : "r"(addr))

#define MMA16816(d, a, b) \
    asm volatile("mma.sync.aligned.m16n8k16.row.col.f32.bf16.bf16.f32 " \
        "{%0,%1,%2,%3}, {%4,%5,%6,%7}, {%8,%9}, {%0,%1,%2,%3};" \
        : "+f"((d)[0]), "+f"((d)[1]), "+f"((d)[2]), "+f"((d)[3]) \
        : "r"((a)[0]), "r"((a)[1]), "r"((a)[2]), "r"((a)[3]), \
          "r"((b)[0]), "r"((b)[1]))

#define CPASYNC16(smem, gmem) \
    asm volatile("cp.async.cg.shared.global [%0], [%1], 16;" \
        :: "r"(smem), "l"(gmem) : "memory")
#define CPCOMMIT() asm volatile("cp.async.commit_group;" ::: "memory")
#define CPWAIT(n)  asm volatile("cp.async.wait_group %0;" :: "n"(n) : "memory")

// ---------------------------------------------------------------------------
// Kernel 0: relative-position bias table
// ---------------------------------------------------------------------------
__global__ void bias_kernel(const float* __restrict__ rel_pos)
{
    int i = blockIdx.x * blockDim.x + threadIdx.x;
    int head = i >> 12;
    int q = (i >> 6) & 63, k = i & 63;
    int qi = q >> 3, qj = q & 7, ki = k >> 3, kj = k & 7;
    int idx = (qi - ki + 7) * 15 + (qj - kj + 7);
    g_bias[i] = rel_pos[idx * NHEAD + head];
}

// ---------------------------------------------------------------------------
// Kernel 0b: transpose + hi/lo split of weights: wt[n][k] = w[k][n]
// ---------------------------------------------------------------------------
__global__ void wsplit_qkv_kernel(const float* __restrict__ w)
{
    int i = blockIdx.x * blockDim.x + threadIdx.x;   // NQKV*512
    int n = i >> 9, k = i & 511;
    float v = w[(size_t)k * NQKV + n];
    __nv_bfloat16 h = __float2bfloat16(v);
    g_wqkv_hi[i] = h;
    g_wqkv_lo[i] = __float2bfloat16(v - __bfloat162float(h));
}
__global__ void wsplit_out_kernel(const float* __restrict__ w)
{
    int i = blockIdx.x * blockDim.x + threadIdx.x;   // 512*512
    int n = i >> 9, k = i & 511;
    float v = w[(size_t)k * CC + n];
    __nv_bfloat16 h = __float2bfloat16(v);
    g_wout_hi[i] = h;
    g_wout_lo[i] = __float2bfloat16(v - __bfloat162float(h));
}

// ---------------------------------------------------------------------------
// Kernel 0c: shift-gather x into window-row order + hi/lo split to bf16
//   each thread: 8 consecutive k of one row
// ---------------------------------------------------------------------------
__global__ __launch_bounds__(256)
void xsplit_kernel(const float* __restrict__ x)
{
    int g = blockIdx.x * blockDim.x + threadIdx.x;   // MROWS*64 units of 8
    int m = g >> 6;
    int ku = (g & 63) * 8;
    int win = m >> 6, t = m & 63;
    int b = win >> 6, whi = (win >> 3) & 7, wwi = win & 7;
    int ph = t >> 3, pw = t & 7;
    int h = (whi * 8 + ph + 4) & 63;
    int w = (wwi * 8 + pw + 4) & 63;
    const float* src = x + ((size_t)((b * 64 + h) * 64 + w)) * CC + ku;
    float4 v0 = *(const float4*)src;
    float4 v1 = *(const float4*)(src + 4);
    float vv[8] = { v0.x, v0.y, v0.z, v0.w, v1.x, v1.y, v1.z, v1.w };
    uint4 hp, lp;
    float hh[8];
    #pragma unroll
    for (int e = 0; e < 8; e++)
        hh[e] = __bfloat162float(__float2bfloat16(vv[e]));
    hp.x = pack2(hh[0], hh[1]); hp.y = pack2(hh[2], hh[3]);
    hp.z = pack2(hh[4], hh[5]); hp.w = pack2(hh[6], hh[7]);
    lp.x = pack2(vv[0] - hh[0], vv[1] - hh[1]);
    lp.y = pack2(vv[2] - hh[2], vv[3] - hh[3]);
    lp.z = pack2(vv[4] - hh[4], vv[5] - hh[5]);
    lp.w = pack2(vv[6] - hh[6], vv[7] - hh[7]);
    size_t o = (size_t)m * CC + ku;
    *(uint4*)(g_a_hi + o) = hp;
    *(uint4*)(g_a_lo + o) = lp;
}

// ---------------------------------------------------------------------------
// mma.sync GEMM: C[m, n0:n0+128] = A[m, :512] @ W[:, n0:n0+128] + bias
//   All operands pre-split bf16 in gmem; cp.async staging, 2 stages.
//   smem rows padded to 80B: (20r+4u) mod 32 perfect bank partition.
//   MODE 0: A = g_a_*,  C -> g_qkv fp32
//   MODE 1: A = g_o_*,  C -> scatter d_out (reverse shift)
// ---------------------------------------------------------------------------
#define RSTRIDE 80
#define T_AH    0
#define T_AL    10240
#define T_BH    20480
#define T_BL    30720
#define STAGE   40960
#define NCHUNK  16

template<int MODE>
__global__ __launch_bounds__(256)
void mma_gemm_kernel(const float* __restrict__ bias,
                     float* __restrict__ outp)
{
    extern __shared__ __align__(16) char dsa[];
    const uint32_t sb = smem_u32(dsa);

    const int tid  = threadIdx.x;
    const int lane = tid & 31, wid = tid >> 5;
    const int bm   = blockIdx.y;
    const int n0   = blockIdx.x * 128;

    // ---- cp.async loader geometry: r = tid>>2 (0..63), u = tid&3 ----
    const int r = tid >> 2, u = tid & 3;
    const __nv_bfloat16* ah = (MODE == 0 ? g_a_hi : g_o_hi)
                              + (size_t)(bm * 128 + r) * CC + u * 8;
    const __nv_bfloat16* al = (MODE == 0 ? g_a_lo : g_o_lo)
                              + (size_t)(bm * 128 + r) * CC + u * 8;
    const __nv_bfloat16* bh = (MODE == 0 ? g_wqkv_hi : g_wout_hi)
                              + (size_t)(n0 + r) * CC + u * 8;
    const __nv_bfloat16* bl = (MODE == 0 ? g_wqkv_lo : g_wout_lo)
                              + (size_t)(n0 + r) * CC + u * 8;
    const uint32_t s_a = (uint32_t)r * RSTRIDE + u * 16;
    const uint32_t s_b = (uint32_t)(r + 64) * RSTRIDE + u * 16;
    const size_t rowskip = (size_t)64 * CC;

    float acc[4][4][4];
    #pragma unroll
    for (int i = 0; i < 4; i++)
        #pragma unroll
        for (int j = 0; j < 4; j++)
            #pragma unroll
            for (int e = 0; e < 4; e++) acc[i][j][e] = 0.0f;

    const int wm = wid >> 2;   // m-half (64 rows)
    const int wn = wid & 3;    // n-quarter (32 cols)

    // ---- issue helper (macro to keep everything in regs) ----
#define ISSUE(c, stg_off) do {                                                \
    const uint32_t _d = sb + (stg_off);                                       \
    const int _k = (c) * 32;                                                  \
    CPASYNC16(_d + T_AH + s_a, ah + _k);                                      \
    CPASYNC16(_d + T_AH + s_b, ah + rowskip + _k);                            \
    CPASYNC16(_d + T_AL + s_a, al + _k);                                      \
    CPASYNC16(_d + T_AL + s_b, al + rowskip + _k);                            \
    CPASYNC16(_d + T_BH + s_a, bh + _k);                                      \
    CPASYNC16(_d + T_BH + s_b, bh + rowskip + _k);                            \
    CPASYNC16(_d + T_BL + s_a, bl + _k);                                      \
    CPASYNC16(_d + T_BL + s_b, bl + rowskip + _k);                            \
    CPCOMMIT();                                                               \
} while (0)

    ISSUE(0, 0);

    for (int c = 0; c < NCHUNK; c++) {
        const int s = c & 1;
        const uint32_t stg = sb + (uint32_t)s * STAGE;

        if (c + 1 < NCHUNK) {
            ISSUE(c + 1, (uint32_t)(s ^ 1) * STAGE);
            CPWAIT(1);
        } else {
            CPWAIT(0);
        }
        __syncthreads();

        #pragma unroll
        for (int k16 = 0; k16 < 2; k16++) {
            uint32_t A[4][4], Bh[2][4], Bl[2][4];
            const uint32_t a_off =
                (uint32_t)(wm * 64 + (lane & 15)) * RSTRIDE
                + (uint32_t)(k16 * 2 + (lane >> 4)) * 16;
            #pragma unroll
            for (int i = 0; i < 4; i++)
                LDSM4(A[i][0], A[i][1], A[i][2], A[i][3],
                      stg + T_AH + a_off + i * 16 * RSTRIDE);
            const int mi = lane >> 3;
            const uint32_t b_off =
                (uint32_t)(wn * 32 + ((mi >> 1) << 3) + (lane & 7)) * RSTRIDE
                + (uint32_t)(k16 * 2 + (mi & 1)) * 16;
            #pragma unroll
            for (int jp = 0; jp < 2; jp++)
                LDSM4(Bh[jp][0], Bh[jp][1], Bh[jp][2], Bh[jp][3],
                      stg + T_BH + b_off + jp * 16 * RSTRIDE);
            #pragma unroll
            for (int jp = 0; jp < 2; jp++)
                LDSM4(Bl[jp][0], Bl[jp][1], Bl[jp][2], Bl[jp][3],
                      stg + T_BL + b_off + jp * 16 * RSTRIDE);

            #pragma unroll
            for (int i = 0; i < 4; i++)
                #pragma unroll
                for (int j = 0; j < 4; j++)
                    MMA16816(acc[i][j], A[i], &Bh[j >> 1][(j & 1) * 2]);
            #pragma unroll
            for (int i = 0; i < 4; i++)
                #pragma unroll
                for (int j = 0; j < 4; j++)
                    MMA16816(acc[i][j], A[i], &Bl[j >> 1][(j & 1) * 2]);
            #pragma unroll
            for (int i = 0; i < 4; i++)
                LDSM4(A[i][0], A[i][1], A[i][2], A[i][3],
                      stg + T_AL + a_off + i * 16 * RSTRIDE);
            #pragma unroll
            for (int i = 0; i < 4; i++)
                #pragma unroll
                for (int j = 0; j < 4; j++)
                    MMA16816(acc[i][j], A[i], &Bh[j >> 1][(j & 1) * 2]);
        }
        __syncthreads();
    }
#undef ISSUE

    // ---- epilogue: direct register -> gmem, bias fused ----
    float2 bj4[4];
    #pragma unroll
    for (int j = 0; j < 4; j++)
        bj4[j] = *(const float2*)(bias + n0 + wn * 32 + j * 8 + (lane & 3) * 2);

    #pragma unroll
    for (int i = 0; i < 4; i++) {
        #pragma unroll
        for (int half = 0; half < 2; half++) {
            int m = bm * 128 + wm * 64 + i * 16 + half * 8 + (lane >> 2);
            float* drow;
            if (MODE == 0) {
                drow = g_qkv + (size_t)m * NQKV;
            } else {
                int win = m >> 6, t = m & 63;
                int b = win >> 6, whi = (win >> 3) & 7, wwi = win & 7;
                int ph = t >> 3, pw = t & 7;
                int ho = (whi * 8 + ph + 4) & 63;
                int wo = (wwi * 8 + pw + 4) & 63;
                drow = outp + ((size_t)((b * 64 + ho) * 64 + wo)) * CC;
            }
            #pragma unroll
            for (int j = 0; j < 4; j++) {
                int cb = n0 + wn * 32 + j * 8 + (lane & 3) * 2;
                float2 v;
                v.x = acc[i][j][half * 2 + 0] + bj4[j].x;
                v.y = acc[i][j][half * 2 + 1] + bj4[j].y;
                *(float2*)(drow + cb) = v;
            }
        }
    }
}

// ---------------------------------------------------------------------------
// attention: 128 threads = 2 windows per CTA; scores in registers;
// epilogue writes hi/lo bf16 split for GEMM2.
// ---------------------------------------------------------------------------
__global__ __launch_bounds__(128)
void attn_kernel()
{
    __shared__ float ks[2][64][36];
    __shared__ float vs[2][64][36];

    const int wslot = threadIdx.x >> 6;               // 0..1
    const int win   = blockIdx.x * 2 + wslot;
    const int head  = blockIdx.y;
    const int t     = threadIdx.x & 63;

    const float* base = g_qkv + (size_t)(win * 64) * NQKV + head * 32;

    float qreg[32];
    {
        const float* qp = base + (size_t)t * NQKV;
        const float* kp = qp + 512;
        const float* vp = qp + 1024;
        #pragma unroll
        for (int d4 = 0; d4 < 8; d4++) {
            float4 qv = *(const float4*)(qp + d4 * 4);
            qreg[d4 * 4 + 0] = qv.x; qreg[d4 * 4 + 1] = qv.y;
            qreg[d4 * 4 + 2] = qv.z; qreg[d4 * 4 + 3] = qv.w;
            float4 kv = *(const float4*)(kp + d4 * 4);
            ks[wslot][t][d4 * 4 + 0] = kv.x; ks[wslot][t][d4 * 4 + 1] = kv.y;
            ks[wslot][t][d4 * 4 + 2] = kv.z; ks[wslot][t][d4 * 4 + 3] = kv.w;
            float4 vv = *(const float4*)(vp + d4 * 4);
            vs[wslot][t][d4 * 4 + 0] = vv.x; vs[wslot][t][d4 * 4 + 1] = vv.y;
            vs[wslot][t][d4 * 4 + 2] = vv.z; vs[wslot][t][d4 * 4 + 3] = vv.w;
        }
    }
    __syncthreads();

    const float scale = 0.17677669529663687f;
    const float* biasrow = g_bias + ((head * 64) + t) * 64;

    float s[64];
    #pragma unroll 8
    for (int kk = 0; kk < 64; kk++) {
        float acc = 0.0f;
        #pragma unroll
        for (int d4 = 0; d4 < 8; d4++) {
            float4 kv = *(const float4*)&ks[wslot][kk][d4 * 4];
            acc = fmaf(qreg[d4 * 4 + 0], kv.x, acc);
            acc = fmaf(qreg[d4 * 4 + 1], kv.y, acc);
            acc = fmaf(qreg[d4 * 4 + 2], kv.z, acc);
            acc = fmaf(qreg[d4 * 4 + 3], kv.w, acc);
        }
        s[kk] = acc * scale + biasrow[kk];
    }

    float mx = -1e30f;
    #pragma unroll
    for (int kk = 0; kk < 64; kk++) mx = fmaxf(mx, s[kk]);
    float sum = 0.0f;
    #pragma unroll
    for (int kk = 0; kk < 64; kk++) {
        float e = __expf(s[kk] - mx);
        s[kk] = e;
        sum += e;
    }
    const float inv = 1.0f / sum;

    float o[32];
    #pragma unroll
    for (int d = 0; d < 32; d++) o[d] = 0.0f;
    #pragma unroll 8
    for (int kk = 0; kk < 64; kk++) {
        float p = s[kk];
        #pragma unroll
        for (int d4 = 0; d4 < 8; d4++) {
            float4 vv = *(const float4*)&vs[wslot][kk][d4 * 4];
            o[d4 * 4 + 0] = fmaf(p, vv.x, o[d4 * 4 + 0]);
            o[d4 * 4 + 1] = fmaf(p, vv.y, o[d4 * 4 + 1]);
            o[d4 * 4 + 2] = fmaf(p, vv.z, o[d4 * 4 + 2]);
            o[d4 * 4 + 3] = fmaf(p, vv.w, o[d4 * 4 + 3]);
        }
    }

    // split-store bf16 hi/lo
    size_t off = (size_t)(win * 64 + t) * CC + head * 32;
    uint4 hp, lp;
    #pragma unroll
    for (int d8 = 0; d8 < 4; d8++) {
        float vv[8], hh[8];
        #pragma unroll
        for (int e = 0; e < 8; e++) {
            vv[e] = o[d8 * 8 + e] * inv;
            hh[e] = __bfloat162float(__float2bfloat16(vv[e]));
        }
        hp.x = pack2(hh[0], hh[1]); hp.y = pack2(hh[2], hh[3]);
        hp.z = pack2(hh[4], hh[5]); hp.w = pack2(hh[6], hh[7]);
        lp.x = pack2(vv[0] - hh[0], vv[1] - hh[1]);
        lp.y = pack2(vv[2] - hh[2], vv[3] - hh[3]);
        lp.z = pack2(vv[4] - hh[4], vv[5] - hh[5]);
        lp.w = pack2(vv[6] - hh[6], vv[7] - hh[7]);
        *(uint4*)(g_o_hi + off + d8 * 8) = hp;
        *(uint4*)(g_o_lo + off + d8 * 8) = lp;
    }
}

// ---------------------------------------------------------------------------
// launch
// ---------------------------------------------------------------------------
extern "C" void kernel_launch(void* const* d_in, const int* in_sizes, int n_in,
                              void* d_out, int out_size)
{
    const float* x       = (const float*)d_in[0];
    const float* w_qkv   = (const float*)d_in[1];
    const float* b_qkv   = (const float*)d_in[2];
    const float* rel_pos = (const float*)d_in[3];
    const float* w_out   = (const float*)d_in[4];
    const float* b_out   = (const float*)d_in[5];
    float* out = (float*)d_out;

    const int dyn = 2 * STAGE;      // 81920 bytes
    cudaFuncSetAttribute(mma_gemm_kernel<0>,
                         cudaFuncAttributeMaxDynamicSharedMemorySize, dyn);
    cudaFuncSetAttribute(mma_gemm_kernel<1>,
                         cudaFuncAttributeMaxDynamicSharedMemorySize, dyn);

    bias_kernel<<<64, 1024>>>(rel_pos);
    wsplit_qkv_kernel<<<(NQKV * CC) / 256, 256>>>(w_qkv);
    wsplit_out_kernel<<<(CC * CC) / 256, 256>>>(w_out);
    xsplit_kernel<<<(MROWS * 64) / 256, 256>>>(x);

    mma_gemm_kernel<0><<<dim3(NQKV / 128, MROWS / 128), 256, dyn>>>(b_qkv, nullptr);
    attn_kernel<<<dim3(512, NHEAD), 128>>>();
    mma_gemm_kernel<1><<<dim3(CC / 128, MROWS / 128), 256, dyn>>>(b_out, out);
}

// round 5
// speedup vs baseline: 2.3522x; 1.2344x over previous
#include <cuda_runtime.h>
#include <cuda_bf16.h>
#include <cstdint>

// ---------------------------------------------------------------------------
// WMSA: B=16 H=W=64 C=512, window 8x8 (shift 4), 16 heads x 32
//   pre:   gather+split x -> g_a_hi/lo; weights -> transposed hi/lo
//   GEMM1: (65536x512)@(512x1536) -> g_qkvh/g_qkvl (bf16 split, q pre-scaled)
//   attn : mma.sync 3-term bf16 per (window, head) -> g_o_hi/lo
//   GEMM2: (65536x512)@(512x512)  -> out scatter (reverse shift)
// ---------------------------------------------------------------------------
#define CC     512
#define NQKV   1536
#define NHEAD  16
#define MROWS  65536

__device__ float g_bias[NHEAD * 64 * 64];
__device__ __nv_bfloat16 g_a_hi[(size_t)MROWS * CC];
__device__ __nv_bfloat16 g_a_lo[(size_t)MROWS * CC];
__device__ __nv_bfloat16 g_qkvh[(size_t)MROWS * NQKV];
__device__ __nv_bfloat16 g_qkvl[(size_t)MROWS * NQKV];
__device__ __nv_bfloat16 g_o_hi[(size_t)MROWS * CC];
__device__ __nv_bfloat16 g_o_lo[(size_t)MROWS * CC];
__device__ __nv_bfloat16 g_wqkv_hi[(size_t)NQKV * CC];
__device__ __nv_bfloat16 g_wqkv_lo[(size_t)NQKV * CC];
__device__ __nv_bfloat16 g_wout_hi[(size_t)CC * CC];
__device__ __nv_bfloat16 g_wout_lo[(size_t)CC * CC];

// ------------------------------- helpers -----------------------------------
__device__ __forceinline__ uint32_t smem_u32(const void* p) {
    uint32_t a;
    asm("{ .reg .u64 t; cvta.to.shared.u64 t, %1; cvt.u32.u64 %0, t; }"
        : "=r"(a) : "l"(p));
    return a;
}
__device__ __forceinline__ uint32_t pack2(float a, float b) {
    __nv_bfloat162 h = __floats2bfloat162_rn(a, b);
    return *(uint32_t*)&h;
}
__device__ __forceinline__ void split2(float a, float b,
                                       uint32_t& hi, uint32_t& lo) {
    float ha = __bfloat162float(__float2bfloat16(a));
    float hb = __bfloat162float(__float2bfloat16(b));
    hi = pack2(ha, hb);
    lo = pack2(a - ha, b - hb);
}

#define LDSM4(r0, r1, r2, r3, addr) \
    asm volatile("ldmatrix.sync.aligned.m8n8.x4.shared.b16 {%0,%1,%2,%3}, [%4];" \
        : "=r"(r0), "=r"(r1), "=r"(r2), "=r"(r3) : "r"(addr))
#define LDSM4T(r0, r1, r2, r3, addr) \
    asm volatile("ldmatrix.sync.aligned.m8n8.x4.trans.shared.b16 {%0,%1,%2,%3}, [%4];" \
        : "=r"(r0), "=r"(r1), "=r"(r2), "=r"(r3) : "r"(addr))

#define MMA16816(d, a, b) \
    asm volatile("mma.sync.aligned.m16n8k16.row.col.f32.bf16.bf16.f32 " \
        "{%0,%1,%2,%3}, {%4,%5,%6,%7}, {%8,%9}, {%0,%1,%2,%3};" \
        : "+f"((d)[0]), "+f"((d)[1]), "+f"((d)[2]), "+f"((d)[3]) \
        : "r"((a)[0]), "r"((a)[1]), "r"((a)[2]), "r"((a)[3]), \
          "r"((b)[0]), "r"((b)[1]))

#define CPASYNC16(smem, gmem) \
    asm volatile("cp.async.cg.shared.global [%0], [%1], 16;" \
        :: "r"(smem), "l"(gmem) : "memory")
#define CPCOMMIT() asm volatile("cp.async.commit_group;" ::: "memory")
#define CPWAIT(n)  asm volatile("cp.async.wait_group %0;" :: "n"(n) : "memory")

#define QK_SCALE 0.17677669529663687f

// ---------------------------------------------------------------------------
// Kernel 0: relative-position bias table
// ---------------------------------------------------------------------------
__global__ void bias_kernel(const float* __restrict__ rel_pos)
{
    int i = blockIdx.x * blockDim.x + threadIdx.x;
    int head = i >> 12;
    int q = (i >> 6) & 63, k = i & 63;
    int qi = q >> 3, qj = q & 7, ki = k >> 3, kj = k & 7;
    int idx = (qi - ki + 7) * 15 + (qj - kj + 7);
    g_bias[i] = rel_pos[idx * NHEAD + head];
}

// ---------------------------------------------------------------------------
// Kernel 0b: transpose + hi/lo split of weights
// ---------------------------------------------------------------------------
__global__ void wsplit_qkv_kernel(const float* __restrict__ w)
{
    int i = blockIdx.x * blockDim.x + threadIdx.x;
    int n = i >> 9, k = i & 511;
    float v = w[(size_t)k * NQKV + n];
    __nv_bfloat16 h = __float2bfloat16(v);
    g_wqkv_hi[i] = h;
    g_wqkv_lo[i] = __float2bfloat16(v - __bfloat162float(h));
}
__global__ void wsplit_out_kernel(const float* __restrict__ w)
{
    int i = blockIdx.x * blockDim.x + threadIdx.x;
    int n = i >> 9, k = i & 511;
    float v = w[(size_t)k * CC + n];
    __nv_bfloat16 h = __float2bfloat16(v);
    g_wout_hi[i] = h;
    g_wout_lo[i] = __float2bfloat16(v - __bfloat162float(h));
}

// ---------------------------------------------------------------------------
// Kernel 0c: shift-gather x + hi/lo split
// ---------------------------------------------------------------------------
__global__ __launch_bounds__(256)
void xsplit_kernel(const float* __restrict__ x)
{
    int g = blockIdx.x * blockDim.x + threadIdx.x;
    int m = g >> 6;
    int ku = (g & 63) * 8;
    int win = m >> 6, t = m & 63;
    int b = win >> 6, whi = (win >> 3) & 7, wwi = win & 7;
    int ph = t >> 3, pw = t & 7;
    int h = (whi * 8 + ph + 4) & 63;
    int w = (wwi * 8 + pw + 4) & 63;
    const float* src = x + ((size_t)((b * 64 + h) * 64 + w)) * CC + ku;
    float4 v0 = *(const float4*)src;
    float4 v1 = *(const float4*)(src + 4);
    float vv[8] = { v0.x, v0.y, v0.z, v0.w, v1.x, v1.y, v1.z, v1.w };
    uint4 hp, lp;
    split2(vv[0], vv[1], hp.x, lp.x);
    split2(vv[2], vv[3], hp.y, lp.y);
    split2(vv[4], vv[5], hp.z, lp.z);
    split2(vv[6], vv[7], hp.w, lp.w);
    size_t o = (size_t)m * CC + ku;
    *(uint4*)(g_a_hi + o) = hp;
    *(uint4*)(g_a_lo + o) = lp;
}

// ---------------------------------------------------------------------------
// mma.sync GEMM (3-term bf16 split), cp.async staged, 2 stages.
//   MODE 0: A = g_a_*, C -> g_qkvh/g_qkvl (split store, q cols pre-scaled)
//   MODE 1: A = g_o_*, C -> scatter d_out fp32 (reverse shift)
// ---------------------------------------------------------------------------
#define RSTRIDE 80
#define T_AH    0
#define T_AL    10240
#define T_BH    20480
#define T_BL    30720
#define STAGE   40960
#define NCHUNK  16

template<int MODE>
__global__ __launch_bounds__(256)
void mma_gemm_kernel(const float* __restrict__ bias,
                     float* __restrict__ outp)
{
    extern __shared__ __align__(16) char dsa[];
    const uint32_t sb = smem_u32(dsa);

    const int tid  = threadIdx.x;
    const int lane = tid & 31, wid = tid >> 5;
    const int bm   = blockIdx.y;
    const int n0   = blockIdx.x * 128;

    const int r = tid >> 2, u = tid & 3;
    const __nv_bfloat16* ah = (MODE == 0 ? g_a_hi : g_o_hi)
                              + (size_t)(bm * 128 + r) * CC + u * 8;
    const __nv_bfloat16* al = (MODE == 0 ? g_a_lo : g_o_lo)
                              + (size_t)(bm * 128 + r) * CC + u * 8;
    const __nv_bfloat16* bh = (MODE == 0 ? g_wqkv_hi : g_wout_hi)
                              + (size_t)(n0 + r) * CC + u * 8;
    const __nv_bfloat16* bl = (MODE == 0 ? g_wqkv_lo : g_wout_lo)
                              + (size_t)(n0 + r) * CC + u * 8;
    const uint32_t s_a = (uint32_t)r * RSTRIDE + u * 16;
    const uint32_t s_b = (uint32_t)(r + 64) * RSTRIDE + u * 16;
    const size_t rowskip = (size_t)64 * CC;

    float acc[4][4][4];
    #pragma unroll
    for (int i = 0; i < 4; i++)
        #pragma unroll
        for (int j = 0; j < 4; j++)
            #pragma unroll
            for (int e = 0; e < 4; e++) acc[i][j][e] = 0.0f;

    const int wm = wid >> 2;
    const int wn = wid & 3;

#define ISSUE(c, stg_off) do {                                                \
    const uint32_t _d = sb + (stg_off);                                       \
    const int _k = (c) * 32;                                                  \
    CPASYNC16(_d + T_AH + s_a, ah + _k);                                      \
    CPASYNC16(_d + T_AH + s_b, ah + rowskip + _k);                            \
    CPASYNC16(_d + T_AL + s_a, al + _k);                                      \
    CPASYNC16(_d + T_AL + s_b, al + rowskip + _k);                            \
    CPASYNC16(_d + T_BH + s_a, bh + _k);                                      \
    CPASYNC16(_d + T_BH + s_b, bh + rowskip + _k);                            \
    CPASYNC16(_d + T_BL + s_a, bl + _k);                                      \
    CPASYNC16(_d + T_BL + s_b, bl + rowskip + _k);                            \
    CPCOMMIT();                                                               \
} while (0)

    ISSUE(0, 0);

    for (int c = 0; c < NCHUNK; c++) {
        const int s = c & 1;
        const uint32_t stg = sb + (uint32_t)s * STAGE;

        if (c + 1 < NCHUNK) {
            ISSUE(c + 1, (uint32_t)(s ^ 1) * STAGE);
            CPWAIT(1);
        } else {
            CPWAIT(0);
        }
        __syncthreads();

        #pragma unroll
        for (int k16 = 0; k16 < 2; k16++) {
            uint32_t A[4][4], Bh[2][4], Bl[2][4];
            const uint32_t a_off =
                (uint32_t)(wm * 64 + (lane & 15)) * RSTRIDE
                + (uint32_t)(k16 * 2 + (lane >> 4)) * 16;
            #pragma unroll
            for (int i = 0; i < 4; i++)
                LDSM4(A[i][0], A[i][1], A[i][2], A[i][3],
                      stg + T_AH + a_off + i * 16 * RSTRIDE);
            const int mi = lane >> 3;
            const uint32_t b_off =
                (uint32_t)(wn * 32 + ((mi >> 1) << 3) + (lane & 7)) * RSTRIDE
                + (uint32_t)(k16 * 2 + (mi & 1)) * 16;
            #pragma unroll
            for (int jp = 0; jp < 2; jp++)
                LDSM4(Bh[jp][0], Bh[jp][1], Bh[jp][2], Bh[jp][3],
                      stg + T_BH + b_off + jp * 16 * RSTRIDE);
            #pragma unroll
            for (int jp = 0; jp < 2; jp++)
                LDSM4(Bl[jp][0], Bl[jp][1], Bl[jp][2], Bl[jp][3],
                      stg + T_BL + b_off + jp * 16 * RSTRIDE);

            #pragma unroll
            for (int i = 0; i < 4; i++)
                #pragma unroll
                for (int j = 0; j < 4; j++)
                    MMA16816(acc[i][j], A[i], &Bh[j >> 1][(j & 1) * 2]);
            #pragma unroll
            for (int i = 0; i < 4; i++)
                #pragma unroll
                for (int j = 0; j < 4; j++)
                    MMA16816(acc[i][j], A[i], &Bl[j >> 1][(j & 1) * 2]);
            #pragma unroll
            for (int i = 0; i < 4; i++)
                LDSM4(A[i][0], A[i][1], A[i][2], A[i][3],
                      stg + T_AL + a_off + i * 16 * RSTRIDE);
            #pragma unroll
            for (int i = 0; i < 4; i++)
                #pragma unroll
                for (int j = 0; j < 4; j++)
                    MMA16816(acc[i][j], A[i], &Bh[j >> 1][(j & 1) * 2]);
        }
        __syncthreads();
    }
#undef ISSUE

    // ---- epilogue ----
    float2 bj4[4];
    #pragma unroll
    for (int j = 0; j < 4; j++)
        bj4[j] = *(const float2*)(bias + n0 + wn * 32 + j * 8 + (lane & 3) * 2);

    const float qs = (MODE == 0 && n0 < 512) ? QK_SCALE : 1.0f;

    #pragma unroll
    for (int i = 0; i < 4; i++) {
        #pragma unroll
        for (int half = 0; half < 2; half++) {
            int m = bm * 128 + wm * 64 + i * 16 + half * 8 + (lane >> 2);
            #pragma unroll
            for (int j = 0; j < 4; j++) {
                int cb = n0 + wn * 32 + j * 8 + (lane & 3) * 2;
                float vx = (acc[i][j][half * 2 + 0] + bj4[j].x) * qs;
                float vy = (acc[i][j][half * 2 + 1] + bj4[j].y) * qs;
                if (MODE == 0) {
                    uint32_t hi, lo;
                    split2(vx, vy, hi, lo);
                    size_t off = (size_t)m * NQKV + cb;
                    *(uint32_t*)(g_qkvh + off) = hi;
                    *(uint32_t*)(g_qkvl + off) = lo;
                } else {
                    int win = m >> 6, t = m & 63;
                    int b = win >> 6, whi = (win >> 3) & 7, wwi = win & 7;
                    int ph = t >> 3, pw = t & 7;
                    int ho = (whi * 8 + ph + 4) & 63;
                    int wo = (wwi * 8 + pw + 4) & 63;
                    float* dst = outp + ((size_t)((b * 64 + ho) * 64 + wo)) * CC + cb;
                    float2 v; v.x = vx; v.y = vy;
                    *(float2*)dst = v;
                }
            }
        }
    }
}

// ---------------------------------------------------------------------------
// Tensor-core attention: CTA = 128 thr = 1 window x 8 heads.
// 4 warps split m (16 rows each). qkv hi/lo per head staged via cp.async
// double-buffer. S: 3-term bf16 mma; softmax in fp32 regs; P split in regs;
// PV: 3-term with V frags via ldmatrix.trans. Output split bf16 for GEMM2.
// ---------------------------------------------------------------------------
#define ARS    80
#define ATILE  5120              // 64*80
#define ASTAGE 30720             // 6 tiles
#define NHCTA  8

__global__ __launch_bounds__(128)
void attn_kernel()
{
    extern __shared__ __align__(16) char asmem[];
    const uint32_t sb = smem_u32(asmem);

    const int tid  = threadIdx.x;
    const int lane = tid & 31, w = tid >> 5;
    const int win  = blockIdx.x;
    const int hb   = blockIdx.y * NHCTA;

    // cp.async chunk map: 1536 16B chunks/stage -> 12 per thread
    const __nv_bfloat16* gsrc[12];
    uint32_t sdst[12];
    #pragma unroll
    for (int i = 0; i < 12; i++) {
        int c = tid + i * 128;
        int tile = c >> 8;            // 0..5 : qh,ql,kh,kl,vh,vl
        int row  = (c >> 2) & 63;
        int unit = c & 3;
        const __nv_bfloat16* base = (tile & 1) ? g_qkvl : g_qkvh;
        gsrc[i] = base + (size_t)(win * 64 + row) * NQKV
                  + (tile >> 1) * 512 + hb * 32 + unit * 8;
        sdst[i] = (uint32_t)tile * ATILE + (uint32_t)row * ARS + unit * 16;
    }

    auto issue = [&](int h, uint32_t stoff) {
        #pragma unroll
        for (int i = 0; i < 12; i++)
            CPASYNC16(sb + stoff + sdst[i], gsrc[i] + h * 32);
        CPCOMMIT();
    };

    issue(0, 0);
    issue(1, ASTAGE);

    const int rr = lane >> 2;                  // row-in-m16 (and +8)
    const int cc2 = (lane & 3) * 2;

    for (int h = 0; h < NHCTA; h++) {
        if (h < NHCTA - 1) { CPWAIT(1); } else { CPWAIT(0); }
        __syncthreads();

        const uint32_t st  = sb + (uint32_t)(h & 1) * ASTAGE;
        const uint32_t qhB = st,            qlB = st + ATILE;
        const uint32_t khB = st + 2*ATILE,  klB = st + 3*ATILE;
        const uint32_t vhB = st + 4*ATILE,  vlB = st + 5*ATILE;
        const int head = hb + h;

        // ---- S = (q*scale) k^T : 3-term ----
        float sacc[8][4];
        #pragma unroll
        for (int j = 0; j < 8; j++)
            #pragma unroll
            for (int e = 0; e < 4; e++) sacc[j][e] = 0.0f;

        #pragma unroll
        for (int ks = 0; ks < 2; ks++) {
            uint32_t Aq[4], Al[4];
            const uint32_t aoff =
                (uint32_t)(w * 16 + (lane & 15)) * ARS
                + (uint32_t)((lane >> 4) + ks * 2) * 16;
            LDSM4(Aq[0], Aq[1], Aq[2], Aq[3], qhB + aoff);
            LDSM4(Al[0], Al[1], Al[2], Al[3], qlB + aoff);
            const int mi = lane >> 3;
            #pragma unroll
            for (int jp = 0; jp < 4; jp++) {
                uint32_t Bh[4], Bl[4];
                const uint32_t boff =
                    (uint32_t)(jp * 16 + ((mi >> 1) << 3) + (lane & 7)) * ARS
                    + (uint32_t)((mi & 1) + ks * 2) * 16;
                LDSM4(Bh[0], Bh[1], Bh[2], Bh[3], khB + boff);
                LDSM4(Bl[0], Bl[1], Bl[2], Bl[3], klB + boff);
                MMA16816(sacc[2*jp],   Aq, &Bh[0]);
                MMA16816(sacc[2*jp+1], Aq, &Bh[2]);
                MMA16816(sacc[2*jp],   Aq, &Bl[0]);
                MMA16816(sacc[2*jp+1], Aq, &Bl[2]);
                MMA16816(sacc[2*jp],   Al, &Bh[0]);
                MMA16816(sacc[2*jp+1], Al, &Bh[2]);
            }
        }

        // ---- bias + softmax (rows rr and rr+8) ----
        const float* bp = g_bias + ((size_t)head * 64 + w * 16 + rr) * 64 + cc2;
        float mx0 = -1e30f, mx1 = -1e30f;
        #pragma unroll
        for (int j = 0; j < 8; j++) {
            float2 b0 = *(const float2*)(bp + j * 8);
            float2 b1 = *(const float2*)(bp + 512 + j * 8);
            sacc[j][0] += b0.x; sacc[j][1] += b0.y;
            sacc[j][2] += b1.x; sacc[j][3] += b1.y;
            mx0 = fmaxf(mx0, fmaxf(sacc[j][0], sacc[j][1]));
            mx1 = fmaxf(mx1, fmaxf(sacc[j][2], sacc[j][3]));
        }
        mx0 = fmaxf(mx0, __shfl_xor_sync(0xffffffff, mx0, 1));
        mx0 = fmaxf(mx0, __shfl_xor_sync(0xffffffff, mx0, 2));
        mx1 = fmaxf(mx1, __shfl_xor_sync(0xffffffff, mx1, 1));
        mx1 = fmaxf(mx1, __shfl_xor_sync(0xffffffff, mx1, 2));
        float sum0 = 0.0f, sum1 = 0.0f;
        #pragma unroll
        for (int j = 0; j < 8; j++) {
            sacc[j][0] = __expf(sacc[j][0] - mx0);
            sacc[j][1] = __expf(sacc[j][1] - mx0);
            sacc[j][2] = __expf(sacc[j][2] - mx1);
            sacc[j][3] = __expf(sacc[j][3] - mx1);
            sum0 += sacc[j][0] + sacc[j][1];
            sum1 += sacc[j][2] + sacc[j][3];
        }
        sum0 += __shfl_xor_sync(0xffffffff, sum0, 1);
        sum0 += __shfl_xor_sync(0xffffffff, sum0, 2);
        sum1 += __shfl_xor_sync(0xffffffff, sum1, 1);
        sum1 += __shfl_xor_sync(0xffffffff, sum1, 2);
        const float inv0 = 1.0f / sum0, inv1 = 1.0f / sum1;
        #pragma unroll
        for (int j = 0; j < 8; j++) {
            sacc[j][0] *= inv0; sacc[j][1] *= inv0;
            sacc[j][2] *= inv1; sacc[j][3] *= inv1;
        }

        // ---- O = P V : 3-term, P frags from registers ----
        float oacc[4][4];
        #pragma unroll
        for (int j = 0; j < 4; j++)
            #pragma unroll
            for (int e = 0; e < 4; e++) oacc[j][e] = 0.0f;

        #pragma unroll
        for (int ks = 0; ks < 4; ks++) {
            uint32_t ph[4], pl[4];
            split2(sacc[2*ks][0],   sacc[2*ks][1],   ph[0], pl[0]);
            split2(sacc[2*ks][2],   sacc[2*ks][3],   ph[1], pl[1]);
            split2(sacc[2*ks+1][0], sacc[2*ks+1][1], ph[2], pl[2]);
            split2(sacc[2*ks+1][2], sacc[2*ks+1][3], ph[3], pl[3]);

            const uint32_t vrow = (uint32_t)(ks * 16 + (lane & 7)
                                  + ((lane >> 3) & 1) * 8) * ARS;
            #pragma unroll
            for (int dv = 0; dv < 2; dv++) {
                uint32_t Vh[4], Vl[4];
                const uint32_t voff = vrow
                    + (uint32_t)(dv * 16 + (lane >> 4) * 8) * 2;
                LDSM4T(Vh[0], Vh[1], Vh[2], Vh[3], vhB + voff);
                LDSM4T(Vl[0], Vl[1], Vl[2], Vl[3], vlB + voff);
                MMA16816(oacc[2*dv],   ph, &Vh[0]);
                MMA16816(oacc[2*dv+1], ph, &Vh[2]);
                MMA16816(oacc[2*dv],   ph, &Vl[0]);
                MMA16816(oacc[2*dv+1], ph, &Vl[2]);
                MMA16816(oacc[2*dv],   pl, &Vh[0]);
                MMA16816(oacc[2*dv+1], pl, &Vh[2]);
            }
        }

        // ---- store O split bf16 ----
        {
            const size_t r0 = (size_t)(win * 64 + w * 16 + rr);
            const int colb = head * 32 + cc2;
            #pragma unroll
            for (int j = 0; j < 4; j++) {
                uint32_t h0, l0, h1, l1;
                split2(oacc[j][0], oacc[j][1], h0, l0);
                split2(oacc[j][2], oacc[j][3], h1, l1);
                size_t o0 = r0 * CC + colb + j * 8;
                size_t o1 = (r0 + 8) * CC + colb + j * 8;
                *(uint32_t*)(g_o_hi + o0) = h0;
                *(uint32_t*)(g_o_lo + o0) = l0;
                *(uint32_t*)(g_o_hi + o1) = h1;
                *(uint32_t*)(g_o_lo + o1) = l1;
            }
        }

        __syncthreads();
        if (h + 2 < NHCTA) issue(h + 2, (uint32_t)(h & 1) * ASTAGE);
    }
}

// ---------------------------------------------------------------------------
// launch
// ---------------------------------------------------------------------------
extern "C" void kernel_launch(void* const* d_in, const int* in_sizes, int n_in,
                              void* d_out, int out_size)
{
    const float* x       = (const float*)d_in[0];
    const float* w_qkv   = (const float*)d_in[1];
    const float* b_qkv   = (const float*)d_in[2];
    const float* rel_pos = (const float*)d_in[3];
    const float* w_out   = (const float*)d_in[4];
    const float* b_out   = (const float*)d_in[5];
    float* out = (float*)d_out;

    const int dyn = 2 * STAGE;      // 81920
    cudaFuncSetAttribute(mma_gemm_kernel<0>,
                         cudaFuncAttributeMaxDynamicSharedMemorySize, dyn);
    cudaFuncSetAttribute(mma_gemm_kernel<1>,
                         cudaFuncAttributeMaxDynamicSharedMemorySize, dyn);
    const int adyn = 2 * ASTAGE;    // 61440
    cudaFuncSetAttribute(attn_kernel,
                         cudaFuncAttributeMaxDynamicSharedMemorySize, adyn);

    bias_kernel<<<64, 1024>>>(rel_pos);
    wsplit_qkv_kernel<<<(NQKV * CC) / 256, 256>>>(w_qkv);
    wsplit_out_kernel<<<(CC * CC) / 256, 256>>>(w_out);
    xsplit_kernel<<<(MROWS * 64) / 256, 256>>>(x);

    mma_gemm_kernel<0><<<dim3(NQKV / 128, MROWS / 128), 256, dyn>>>(b_qkv, nullptr);
    attn_kernel<<<dim3(1024, NHEAD / NHCTA), 128, adyn>>>();
    mma_gemm_kernel<1><<<dim3(CC / 128, MROWS / 128), 256, dyn>>>(b_out, out);
}